// round 9
// baseline (speedup 1.0000x reference)
#include <cuda_runtime.h>

// ---------------------------------------------------------------------------
// LSTMActor two-phase, scalar-FMA version (no inline-asm packing):
//   P1: per-thread 2-layer LSTM (T=24) -> feats scratch [b/128][96][128] f4
//   P2: FC1(386->128)+ReLU -> FC2(128->24) -> softsign, 2 threads/sample
// ---------------------------------------------------------------------------

#define TT   24
#define OBSC 74
#define MAXB 262144

// ---- packed small-weight table (g_small) offsets, in floats ----
// PK1 : [k=0..10][row 0..31]  (rows: i0-7,f0-7,g0-7,o0-7)
// PK2 : [k=0..23][row 0..63]  (rows: i0-15,f0-15,g0-15,o0-15)
// B1  : [32]  b_ih1+b_hh1
// B2  : [64]  b_ih2+b_hh2
// PINIT : [3][128]  fc1_b ; fc1_w[:,384] ; fc1_w[:,385]
// PFC2  : [j=0..127][24]  fc2_w transposed
// FB2   : [24]
#define OFF_PK1   0
#define OFF_PK2   352
#define OFF_B1    1888
#define OFF_B2    1920
#define SMALL1_TOT 1984
#define OFF_PINIT 1984
#define OFF_PFC2  2368
#define OFF_FB2   5440
#define SMALL_TOT 5464

#define PACKFC_FLOATS (384*128)   // FC1 weights, [kglobal][j]

__device__ float4 g_packfc4[PACKFC_FLOATS/4];
__device__ __align__(16) float g_small[SMALL_TOT];
// feats: [b>>7][96][128] float4  (r = t*4+i, lane = b&127)
__device__ float4 g_feats4[(size_t)(MAXB/128) * 96 * 128];

// ---------------------------------------------------------------------------
__global__ void pack_kernel(
    const float* __restrict__ w_ih1, const float* __restrict__ w_hh1,
    const float* __restrict__ b_ih1, const float* __restrict__ b_hh1,
    const float* __restrict__ w_ih2, const float* __restrict__ w_hh2,
    const float* __restrict__ b_ih2, const float* __restrict__ b_hh2,
    const float* __restrict__ fc1_w, const float* __restrict__ fc1_b,
    const float* __restrict__ fc2_w, const float* __restrict__ fc2_b)
{
    int i = blockIdx.x * blockDim.x + threadIdx.x;
    if (i < PACKFC_FLOATS) {
        int kg = i >> 7;
        int j  = i & 127;
        ((float*)g_packfc4)[i] = fc1_w[j * 386 + kg];
    }
    int s = i - PACKFC_FLOATS;
    if (s >= 0 && s < SMALL_TOT) {
        float v;
        if (s < 352) {                       // PK1
            int k = s / 32, r = s % 32;
            v = (k < 3) ? w_ih1[r * 3 + k] : w_hh1[r * 8 + (k - 3)];
        } else if (s < 1888) {               // PK2
            int z = s - 352;
            int k = z / 64, r = z % 64;
            v = (k < 8) ? w_ih2[r * 8 + k] : w_hh2[r * 16 + (k - 8)];
        } else if (s < 1920) {               // B1
            int r = s - 1888;
            v = b_ih1[r] + b_hh1[r];
        } else if (s < 1984) {               // B2
            int r = s - 1920;
            v = b_ih2[r] + b_hh2[r];
        } else if (s < 2368) {               // PINIT
            int z = s - 1984;
            int r = z / 128, j = z % 128;
            v = (r == 0) ? fc1_b[j] : fc1_w[j * 386 + 384 + (r - 1)];
        } else if (s < 5440) {               // PFC2
            int z = s - 2368;
            int j = z / 24, a = z % 24;
            v = fc2_w[a * 128 + j];
        } else {                             // FB2
            v = fc2_b[s - 5440];
        }
        g_small[s] = v;
    }
}

// ---------------------------------------------------------------------------
__device__ __forceinline__ float tanh_ap(float x)
{
    float y;
    asm("tanh.approx.f32 %0, %1;" : "=f"(y) : "f"(x));
    return y;
}

__device__ __forceinline__ float sigm(float x)
{
    return fmaf(tanh_ap(0.5f * x), 0.5f, 0.5f);
}

// ---------------------------------------------------------------------------
// Phase 1: LSTM. 128 thr/block, 3 blocks/SM.
// ---------------------------------------------------------------------------
__global__ __launch_bounds__(128, 3) void lstm_kernel(
    const float* __restrict__ obs, int n)
{
    __shared__ __align__(16) float sm[SMALL1_TOT];
    __shared__ __align__(16) float sobs[128 * OBSC];

    for (int i = threadIdx.x; i < SMALL1_TOT; i += 128) sm[i] = g_small[i];

    int base = blockIdx.x * 128;
    {
        size_t total4 = (size_t)n * OBSC / 4;
        size_t b4 = (size_t)base * OBSC / 4;
        const float4* src = reinterpret_cast<const float4*>(obs) + b4;
        float4* dst = reinterpret_cast<float4*>(sobs);
        #pragma unroll 4
        for (int i = threadIdx.x; i < 128 * OBSC / 4; i += 128)
            if (b4 + i < total4) dst[i] = src[i];
    }
    __syncthreads();

    int tid = base + threadIdx.x;
    if (tid >= n) return;

    const float* orow = sobs + threadIdx.x * OBSC;

    float kh[24];
    float c1[8];
    float c2[16];
    #pragma unroll
    for (int i = 0; i < 24; i++) kh[i] = 0.0f;
    #pragma unroll
    for (int i = 0; i < 8; i++)  c1[i] = 0.0f;
    #pragma unroll
    for (int i = 0; i < 16; i++) c2[i] = 0.0f;

    float4* fblk = g_feats4 + (size_t)blockIdx.x * 96 * 128 + threadIdx.x;

    #pragma unroll 1
    for (int t = 0; t < TT; t++) {
        float xv0 = orow[t];
        float xv1 = orow[24 + t];
        float xv2 = orow[48 + t];

        // ---------------- LSTM1 (8 units, 4 gates) ----------------
        float ai[8], af[8], ag[8], ao[8];
        #pragma unroll
        for (int j = 0; j < 8; j++) {
            ai[j] = sm[OFF_B1 + j];
            af[j] = sm[OFF_B1 + 8 + j];
            ag[j] = sm[OFF_B1 + 16 + j];
            ao[j] = sm[OFF_B1 + 24 + j];
        }
        #pragma unroll
        for (int k = 0; k < 11; k++) {
            float xk = (k == 0) ? xv0 : (k == 1) ? xv1 : (k == 2) ? xv2 : kh[k - 3];
            const float* w = &sm[OFF_PK1 + k * 32];
            #pragma unroll
            for (int j4 = 0; j4 < 2; j4++) {
                float4 wi = *reinterpret_cast<const float4*>(w + j4 * 4);
                float4 wf = *reinterpret_cast<const float4*>(w + 8 + j4 * 4);
                float4 wg = *reinterpret_cast<const float4*>(w + 16 + j4 * 4);
                float4 wo = *reinterpret_cast<const float4*>(w + 24 + j4 * 4);
                int j0 = j4 * 4;
                ai[j0]   = fmaf(wi.x, xk, ai[j0]);   ai[j0+1] = fmaf(wi.y, xk, ai[j0+1]);
                ai[j0+2] = fmaf(wi.z, xk, ai[j0+2]); ai[j0+3] = fmaf(wi.w, xk, ai[j0+3]);
                af[j0]   = fmaf(wf.x, xk, af[j0]);   af[j0+1] = fmaf(wf.y, xk, af[j0+1]);
                af[j0+2] = fmaf(wf.z, xk, af[j0+2]); af[j0+3] = fmaf(wf.w, xk, af[j0+3]);
                ag[j0]   = fmaf(wg.x, xk, ag[j0]);   ag[j0+1] = fmaf(wg.y, xk, ag[j0+1]);
                ag[j0+2] = fmaf(wg.z, xk, ag[j0+2]); ag[j0+3] = fmaf(wg.w, xk, ag[j0+3]);
                ao[j0]   = fmaf(wo.x, xk, ao[j0]);   ao[j0+1] = fmaf(wo.y, xk, ao[j0+1]);
                ao[j0+2] = fmaf(wo.z, xk, ao[j0+2]); ao[j0+3] = fmaf(wo.w, xk, ao[j0+3]);
            }
        }
        #pragma unroll
        for (int j = 0; j < 8; j++) {
            float cn = sigm(af[j]) * c1[j] + sigm(ai[j]) * tanh_ap(ag[j]);
            c1[j] = cn;
            kh[j] = sigm(ao[j]) * tanh_ap(cn);   // new h1 (only used by LSTM2 below)
        }

        // ---------------- LSTM2 (16 units, 2 half-blocks of 8) ----------------
        float h2n[16];
        #pragma unroll
        for (int ub = 0; ub < 2; ub++) {
            float bi[8], bf[8], bg[8], bo[8];
            #pragma unroll
            for (int j = 0; j < 8; j++) {
                bi[j] = sm[OFF_B2 + ub * 8 + j];
                bf[j] = sm[OFF_B2 + 16 + ub * 8 + j];
                bg[j] = sm[OFF_B2 + 32 + ub * 8 + j];
                bo[j] = sm[OFF_B2 + 48 + ub * 8 + j];
            }
            #pragma unroll
            for (int k = 0; k < 24; k++) {
                float xk = kh[k];
                const float* w = &sm[OFF_PK2 + k * 64 + ub * 8];
                #pragma unroll
                for (int j4 = 0; j4 < 2; j4++) {
                    float4 wi = *reinterpret_cast<const float4*>(w + j4 * 4);
                    float4 wf = *reinterpret_cast<const float4*>(w + 16 + j4 * 4);
                    float4 wg = *reinterpret_cast<const float4*>(w + 32 + j4 * 4);
                    float4 wo = *reinterpret_cast<const float4*>(w + 48 + j4 * 4);
                    int j0 = j4 * 4;
                    bi[j0]   = fmaf(wi.x, xk, bi[j0]);   bi[j0+1] = fmaf(wi.y, xk, bi[j0+1]);
                    bi[j0+2] = fmaf(wi.z, xk, bi[j0+2]); bi[j0+3] = fmaf(wi.w, xk, bi[j0+3]);
                    bf[j0]   = fmaf(wf.x, xk, bf[j0]);   bf[j0+1] = fmaf(wf.y, xk, bf[j0+1]);
                    bf[j0+2] = fmaf(wf.z, xk, bf[j0+2]); bf[j0+3] = fmaf(wf.w, xk, bf[j0+3]);
                    bg[j0]   = fmaf(wg.x, xk, bg[j0]);   bg[j0+1] = fmaf(wg.y, xk, bg[j0+1]);
                    bg[j0+2] = fmaf(wg.z, xk, bg[j0+2]); bg[j0+3] = fmaf(wg.w, xk, bg[j0+3]);
                    bo[j0]   = fmaf(wo.x, xk, bo[j0]);   bo[j0+1] = fmaf(wo.y, xk, bo[j0+1]);
                    bo[j0+2] = fmaf(wo.z, xk, bo[j0+2]); bo[j0+3] = fmaf(wo.w, xk, bo[j0+3]);
                }
            }
            #pragma unroll
            for (int j = 0; j < 8; j++) {
                int u = ub * 8 + j;
                float cn = sigm(bf[j]) * c2[u] + sigm(bi[j]) * tanh_ap(bg[j]);
                c2[u] = cn;
                h2n[u] = sigm(bo[j]) * tanh_ap(cn);
            }
        }
        #pragma unroll
        for (int u = 0; u < 16; u++) kh[8 + u] = h2n[u];

        // coalesced feats store: [blk][r=t*4+i][lane]
        fblk[(t * 4 + 0) * 128] = make_float4(h2n[0],  h2n[1],  h2n[2],  h2n[3]);
        fblk[(t * 4 + 1) * 128] = make_float4(h2n[4],  h2n[5],  h2n[6],  h2n[7]);
        fblk[(t * 4 + 2) * 128] = make_float4(h2n[8],  h2n[9],  h2n[10], h2n[11]);
        fblk[(t * 4 + 3) * 128] = make_float4(h2n[12], h2n[13], h2n[14], h2n[15]);
    }
}

// ---------------------------------------------------------------------------
// Phase 2: FC. 2 threads per sample, 512 thr/block.
// Thread parity e owns j = 8m+4e+c (m=0..15, c=0..3) -> acc[64] scalar regs.
// smem layout (floats): [0..49151] W1 [kg][j]; PINIT(384); PFC2(3072); FB2(24)
// ---------------------------------------------------------------------------
#define P2_W1    0
#define P2_PINIT 49152
#define P2_PFC2  49536
#define P2_FB2   52608
#define P2_TOT   52632
#define P2_SMEM_BYTES (P2_TOT * 4)   // 210528 B

__global__ __launch_bounds__(512, 1) void fc_kernel(
    const float* __restrict__ obs, float* __restrict__ out, int n)
{
    extern __shared__ __align__(16) float sm2[];
    {
        float4* d4 = reinterpret_cast<float4*>(sm2);
        #pragma unroll 4
        for (int i = threadIdx.x; i < PACKFC_FLOATS / 4; i += 512)
            d4[i] = g_packfc4[i];
        for (int i = threadIdx.x; i < SMALL_TOT - OFF_PINIT; i += 512)
            sm2[P2_PINIT + i] = g_small[OFF_PINIT + i];
    }
    __syncthreads();

    int tid = blockIdx.x * 512 + threadIdx.x;
    if (tid >= 2 * n) return;
    int s = tid >> 1;          // sample
    int e = tid & 1;           // half

    float x2a = obs[(size_t)s * OBSC + 72];
    float x2b = obs[(size_t)s * OBSC + 73];

    float acc[64];
    #pragma unroll
    for (int m = 0; m < 16; m++) {
        #pragma unroll
        for (int c = 0; c < 4; c++) {
            int j = 8 * m + 4 * e + c;
            acc[4 * m + c] = sm2[P2_PINIT + j]
                           + x2a * sm2[P2_PINIT + 128 + j]
                           + x2b * sm2[P2_PINIT + 256 + j];
        }
    }

    const float4* frow = g_feats4 + (size_t)(s >> 7) * 96 * 128 + (s & 127);

    #pragma unroll 1
    for (int k4 = 0; k4 < 96; k4++) {
        float4 f = frow[k4 * 128];
        #pragma unroll
        for (int e4 = 0; e4 < 4; e4++) {
            float fe = (e4 == 0) ? f.x : (e4 == 1) ? f.y : (e4 == 2) ? f.z : f.w;
            const float4* w4 = reinterpret_cast<const float4*>(&sm2[P2_W1 + (k4 * 4 + e4) * 128]) + e;
            #pragma unroll 4
            for (int m = 0; m < 16; m++) {
                float4 w = w4[2 * m];
                acc[4 * m]     = fmaf(w.x, fe, acc[4 * m]);
                acc[4 * m + 1] = fmaf(w.y, fe, acc[4 * m + 1]);
                acc[4 * m + 2] = fmaf(w.z, fe, acc[4 * m + 2]);
                acc[4 * m + 3] = fmaf(w.w, fe, acc[4 * m + 3]);
            }
        }
    }

    // ---------------- ReLU + partial FC2 ----------------
    float y[24];
    #pragma unroll
    for (int a = 0; a < 24; a++)
        y[a] = (e == 0) ? sm2[P2_FB2 + a] : 0.0f;

    #pragma unroll 1
    for (int m = 0; m < 16; m++) {
        #pragma unroll
        for (int c = 0; c < 4; c++) {
            int j = 8 * m + 4 * e + c;
            float xr = fmaxf(acc[4 * m + c], 0.0f);
            const float4* w4 = reinterpret_cast<const float4*>(&sm2[P2_PFC2 + j * 24]);
            #pragma unroll
            for (int a4 = 0; a4 < 6; a4++) {
                float4 w = w4[a4];
                y[4 * a4]     = fmaf(w.x, xr, y[4 * a4]);
                y[4 * a4 + 1] = fmaf(w.y, xr, y[4 * a4 + 1]);
                y[4 * a4 + 2] = fmaf(w.z, xr, y[4 * a4 + 2]);
                y[4 * a4 + 3] = fmaf(w.w, xr, y[4 * a4 + 3]);
            }
        }
    }

    // combine pair partials
    #pragma unroll
    for (int a = 0; a < 24; a++)
        y[a] += __shfl_xor_sync(0xFFFFFFFFu, y[a], 1);

    // softsign + store own 12 contiguous floats
    float* op = out + (size_t)s * 24 + 12 * e;
    #pragma unroll
    for (int g = 0; g < 3; g++) {
        float v0 = y[12 * e + 4 * g];
        float v1 = y[12 * e + 4 * g + 1];
        float v2 = y[12 * e + 4 * g + 2];
        float v3 = y[12 * e + 4 * g + 3];
        float4 o4;
        o4.x = __fdividef(v0, 1.0f + fabsf(v0));
        o4.y = __fdividef(v1, 1.0f + fabsf(v1));
        o4.z = __fdividef(v2, 1.0f + fabsf(v2));
        o4.w = __fdividef(v3, 1.0f + fabsf(v3));
        *reinterpret_cast<float4*>(op + 4 * g) = o4;
    }
}

// ---------------------------------------------------------------------------
extern "C" void kernel_launch(void* const* d_in, const int* in_sizes, int n_in,
                              void* d_out, int out_size)
{
    const float* obs   = (const float*)d_in[0];
    const float* w_ih1 = (const float*)d_in[1];
    const float* w_hh1 = (const float*)d_in[2];
    const float* b_ih1 = (const float*)d_in[3];
    const float* b_hh1 = (const float*)d_in[4];
    const float* w_ih2 = (const float*)d_in[5];
    const float* w_hh2 = (const float*)d_in[6];
    const float* b_ih2 = (const float*)d_in[7];
    const float* b_hh2 = (const float*)d_in[8];
    const float* fc1_w = (const float*)d_in[9];
    const float* fc1_b = (const float*)d_in[10];
    const float* fc2_w = (const float*)d_in[11];
    const float* fc2_b = (const float*)d_in[12];

    int n = in_sizes[0] / OBSC;
    if (n > MAXB) n = MAXB;

    cudaFuncSetAttribute(fc_kernel,
                         cudaFuncAttributeMaxDynamicSharedMemorySize,
                         P2_SMEM_BYTES);

    int pack_items = PACKFC_FLOATS + SMALL_TOT;
    int pack_blocks = (pack_items + 255) / 256;
    pack_kernel<<<pack_blocks, 256>>>(w_ih1, w_hh1, b_ih1, b_hh1,
                                      w_ih2, w_hh2, b_ih2, b_hh2,
                                      fc1_w, fc1_b, fc2_w, fc2_b);

    lstm_kernel<<<(n + 127) / 128, 128>>>(obs, n);
    fc_kernel<<<(2 * n + 511) / 512, 512, P2_SMEM_BYTES>>>(obs, (float*)d_out, n);
}